// round 1
// baseline (speedup 1.0000x reference)
#include <cuda_runtime.h>

// DivEncLayer: out[b,q] = W2_q . ELU(x[b, q*128:(q+1)*128] @ W1_q + b1_q) + b2_q
// B=2048, Q=128, S=128, H=32. All fp32.
//
// Strategy: block = (one q, 128-batch tile). x tile + W1_q staged in SMEM.
// Compute with packed fma.rn.f32x2 (Blackwell FFMA2) for 2x fp32 throughput.

typedef unsigned long long ull_t;

__device__ __forceinline__ ull_t ffma2(ull_t a, ull_t b, ull_t c) {
    ull_t d;
    asm("fma.rn.f32x2 %0, %1, %2, %3;" : "=l"(d) : "l"(a), "l"(b), "l"(c));
    return d;
}
__device__ __forceinline__ ull_t pack2(float lo, float hi) {
    ull_t r;
    asm("mov.b64 %0, {%1, %2};" : "=l"(r) : "f"(lo), "f"(hi));
    return r;
}
__device__ __forceinline__ void unpack2(ull_t v, float& lo, float& hi) {
    asm("mov.b64 {%0, %1}, %2;" : "=f"(lo), "=f"(hi) : "l"(v));
}

#define B_TOT   2048
#define Q_TOT   128
#define S_DIM   128
#define H_DIM   32
#define C_TOT   (Q_TOT * S_DIM)   // 16384
#define BT      128               // batch tile per block
#define XSTRIDE 132               // padded floats per batch row in smem (conflict-free)

// smem layout (floats): sx[128*132] | sW[128*32] | sW2[32] | sB1[32]
#define SX_FLOATS   (BT * XSTRIDE)               // 16896
#define SW_FLOATS   (S_DIM * H_DIM)              // 4096
#define SMEM_FLOATS (SX_FLOATS + SW_FLOATS + 64)
#define SMEM_BYTES  (SMEM_FLOATS * 4)            // 84224 B

__device__ __forceinline__ float elu_f(float v) {
    return v > 0.0f ? v : (expf(v) - 1.0f);
}

extern __shared__ float smem[];

__global__ void __launch_bounds__(256, 2)
divenc_kernel(const float* __restrict__ xg,
              const float* __restrict__ w1g,
              const float* __restrict__ b1g,
              const float* __restrict__ w2g,
              const float* __restrict__ b2g,
              float* __restrict__ out)
{
    float* sx  = smem;                    // [b][s], stride XSTRIDE
    float* sW  = smem + SX_FLOATS;        // [k][h], 32 floats/row = 128B, natural
    float* sW2 = sW + SW_FLOATS;          // [32]
    float* sB1 = sW2 + 32;                // [32]

    const int q  = blockIdx.x;
    const int bt = blockIdx.y;
    const int t  = threadIdx.x;

    // ---- stage x tile: rows = 128 batches, cols = 128 s (coalesced 512B/row) ----
    {
        const size_t base_f4 = ((size_t)bt * BT * (size_t)C_TOT + (size_t)q * S_DIM) >> 2;
        const float4* xg4 = reinterpret_cast<const float4*>(xg);
        #pragma unroll
        for (int idx = t; idx < BT * (S_DIM / 4); idx += 256) {
            int row = idx >> 5;          // batch within tile
            int c4  = idx & 31;          // float4 column
            float4 v = xg4[base_f4 + (size_t)row * (C_TOT / 4) + c4];
            *reinterpret_cast<float4*>(&sx[row * XSTRIDE + c4 * 4]) = v;
        }
        const float4* w14 = reinterpret_cast<const float4*>(w1g + (size_t)q * SW_FLOATS);
        #pragma unroll
        for (int idx = t; idx < SW_FLOATS / 4; idx += 256)
            *reinterpret_cast<float4*>(&sW[idx * 4]) = w14[idx];
        if (t < 32) {
            sW2[t] = w2g[q * H_DIM + t];
            sB1[t] = b1g[q * H_DIM + t];
        }
    }
    __syncthreads();

    // ---- thread mapping ----
    const int w   = t >> 5;      // warp 0..7
    const int l   = t & 31;
    const int th  = l & 7;       // hidden group: h = th*4
    const int tbs = l >> 3;      // 0..3
    const int h   = th * 4;
    const int bb  = w * 16 + tbs;   // local batch base; batches bb + 4*bi, bi=0..3

    ull_t acc[4][2];
    #pragma unroll
    for (int bi = 0; bi < 4; bi++) { acc[bi][0] = 0ULL; acc[bi][1] = 0ULL; }

    // ---- main loop: K = 128, 4 k-steps per iteration ----
    #pragma unroll 2
    for (int k = 0; k < S_DIM; k += 4) {
        float4 xv[4];
        #pragma unroll
        for (int bi = 0; bi < 4; bi++)
            xv[bi] = *reinterpret_cast<const float4*>(&sx[(bb + 4 * bi) * XSTRIDE + k]);

        ulonglong2 wv[4];
        #pragma unroll
        for (int kk = 0; kk < 4; kk++)
            wv[kk] = *reinterpret_cast<const ulonglong2*>(&sW[(k + kk) * H_DIM + h]);

        #pragma unroll
        for (int kk = 0; kk < 4; kk++) {
            #pragma unroll
            for (int bi = 0; bi < 4; bi++) {
                float xs = (kk == 0) ? xv[bi].x :
                           (kk == 1) ? xv[bi].y :
                           (kk == 2) ? xv[bi].z : xv[bi].w;
                ull_t xx = pack2(xs, xs);
                acc[bi][0] = ffma2(xx, wv[kk].x, acc[bi][0]);
                acc[bi][1] = ffma2(xx, wv[kk].y, acc[bi][1]);
            }
        }
    }

    // ---- epilogue: +b1, ELU, dot with W2, 8-lane reduce over th ----
    float w2v[4], b1v[4];
    #pragma unroll
    for (int j = 0; j < 4; j++) { w2v[j] = sW2[h + j]; b1v[j] = sB1[h + j]; }

    float res[4];
    #pragma unroll
    for (int bi = 0; bi < 4; bi++) {
        float h0, h1, h2, h3;
        unpack2(acc[bi][0], h0, h1);
        unpack2(acc[bi][1], h2, h3);
        h0 = elu_f(h0 + b1v[0]);
        h1 = elu_f(h1 + b1v[1]);
        h2 = elu_f(h2 + b1v[2]);
        h3 = elu_f(h3 + b1v[3]);
        float p = h0 * w2v[0] + h1 * w2v[1] + h2 * w2v[2] + h3 * w2v[3];
        p += __shfl_xor_sync(0xffffffffu, p, 1);
        p += __shfl_xor_sync(0xffffffffu, p, 2);
        p += __shfl_xor_sync(0xffffffffu, p, 4);
        res[bi] = p;
    }

    if (th == 0) {
        const float b2q = b2g[q];
        #pragma unroll
        for (int bi = 0; bi < 4; bi++) {
            int b_glob = bt * BT + bb + 4 * bi;
            out[(size_t)b_glob * Q_TOT + q] = res[bi] + b2q;
        }
    }
}

extern "C" void kernel_launch(void* const* d_in, const int* in_sizes, int n_in,
                              void* d_out, int out_size)
{
    const float* x  = (const float*)d_in[0];
    const float* w1 = (const float*)d_in[1];
    const float* b1 = (const float*)d_in[2];
    const float* w2 = (const float*)d_in[3];
    const float* b2 = (const float*)d_in[4];
    float* out = (float*)d_out;

    cudaFuncSetAttribute(divenc_kernel,
                         cudaFuncAttributeMaxDynamicSharedMemorySize, SMEM_BYTES);

    dim3 grid(Q_TOT, B_TOT / BT);   // (128, 16)
    divenc_kernel<<<grid, 256, SMEM_BYTES>>>(x, w1, b1, w2, b2, out);
}

// round 5
// speedup vs baseline: 1.5673x; 1.5673x over previous
#include <cuda_runtime.h>
#include <cstdint>

// DivEncLayer via legacy tensor cores: mma.sync.m16n8k8 tf32 (sm_80+ PTX).
// out[b,q] = W2_q . ELU(x[b, q*128:(q+1)*128] @ W1_q + b1_q) + b2_q
// B=2048, Q=128, S=128(K), H=32(N). Block = (q, 128-batch tile). 2048 blocks.

#define B_TOT 2048
#define Q_TOT 128
#define S_DIM 128
#define H_DIM 32
#define C_TOT 16384
#define BT    128
#define XSTRIDE 132   // floats per row; bank(4g+c) all-distinct for fragment loads

// smem floats: sx[128*132] | swt[32*132] | sb1[32] | sw2[32]
#define SX_F   (BT * XSTRIDE)          // 16896
#define SWT_F  (H_DIM * XSTRIDE)       // 4224
#define SMEM_F (SX_F + SWT_F + 64)
#define SMEM_BYTES (SMEM_F * 4)        // 84736

// tf32 round (RNA): cvt.rna.tf32.f32 needs a .b32 destination.
__device__ __forceinline__ float to_tf32(float x) {
    uint32_t r;
    asm("cvt.rna.tf32.f32 %0, %1;" : "=r"(r) : "f"(x));
    return __uint_as_float(r);
}

__device__ __forceinline__ void mma_tf32(float* d, const uint32_t* a, const uint32_t* b) {
    asm volatile(
        "mma.sync.aligned.m16n8k8.row.col.f32.tf32.tf32.f32 "
        "{%0,%1,%2,%3}, {%4,%5,%6,%7}, {%8,%9}, {%0,%1,%2,%3};"
        : "+f"(d[0]), "+f"(d[1]), "+f"(d[2]), "+f"(d[3])
        : "r"(a[0]), "r"(a[1]), "r"(a[2]), "r"(a[3]), "r"(b[0]), "r"(b[1]));
}

__device__ __forceinline__ float elu_f(float v) {
    return v > 0.0f ? v : (expf(v) - 1.0f);
}

extern __shared__ float smem[];

__global__ void __launch_bounds__(256, 2)
divenc_mma_kernel(const float* __restrict__ xg,
                  const float* __restrict__ w1g,
                  const float* __restrict__ b1g,
                  const float* __restrict__ w2g,
                  const float* __restrict__ b2g,
                  float* __restrict__ out)
{
    float* sx  = smem;               // [m][k], stride 132
    float* swt = smem + SX_F;        // [h][k], stride 132 (W1 transposed)
    float* sb1 = swt + SWT_F;        // [32]
    float* sw2 = sb1 + 32;           // [32]

    const int q  = blockIdx.x;
    const int bt = blockIdx.y;
    const int t  = threadIdx.x;

    // ---- stage x tile (coalesced 512B rows), tf32-convert once ----
    {
        const float4* xg4 = reinterpret_cast<const float4*>(xg);
        const size_t xbase = ((size_t)bt * BT * (size_t)C_TOT + (size_t)q * S_DIM) >> 2;
        #pragma unroll
        for (int idx = t; idx < BT * (S_DIM / 4); idx += 256) {
            int row = idx >> 5;
            int c4  = idx & 31;
            float4 v = xg4[xbase + (size_t)row * (C_TOT / 4) + c4];
            v.x = to_tf32(v.x); v.y = to_tf32(v.y);
            v.z = to_tf32(v.z); v.w = to_tf32(v.w);
            *reinterpret_cast<float4*>(&sx[row * XSTRIDE + c4 * 4]) = v;
        }
    }
    // ---- stage W1^T: W1[k][h] -> swt[h][k], tf32-convert once ----
    {
        const float4* wq4 = reinterpret_cast<const float4*>(w1g + (size_t)q * (S_DIM * H_DIM));
        #pragma unroll
        for (int idx = t; idx < (S_DIM * H_DIM) / 4; idx += 256) {
            int k  = idx >> 3;       // 0..127
            int h4 = idx & 7;        // h group
            float4 wv = wq4[idx];    // W1[k][4h4 .. 4h4+3]
            swt[(h4 * 4 + 0) * XSTRIDE + k] = to_tf32(wv.x);
            swt[(h4 * 4 + 1) * XSTRIDE + k] = to_tf32(wv.y);
            swt[(h4 * 4 + 2) * XSTRIDE + k] = to_tf32(wv.z);
            swt[(h4 * 4 + 3) * XSTRIDE + k] = to_tf32(wv.w);
        }
    }
    if (t < 32) {
        sb1[t] = b1g[q * H_DIM + t];
        sw2[t] = w2g[q * H_DIM + t];
    }
    __syncthreads();

    // ---- per-warp tile: M=16 rows, N=32 (4 n-tiles of 8), K=128 ----
    const int w = t >> 5;
    const int l = t & 31;
    const int g = l >> 2;     // 0..7
    const int c = l & 3;      // 0..3
    const int m0 = w * 16;

    float acc[4][4];
    #pragma unroll
    for (int j = 0; j < 4; j++)
        #pragma unroll
        for (int i = 0; i < 4; i++) acc[j][i] = 0.0f;

    const uint32_t* sxu  = reinterpret_cast<const uint32_t*>(sx);
    const uint32_t* swtu = reinterpret_cast<const uint32_t*>(swt);
    const int arow0 = (m0 + g) * XSTRIDE + c;       // A row g
    const int arow1 = (m0 + g + 8) * XSTRIDE + c;   // A row g+8

    #pragma unroll 4
    for (int s = 0; s < 16; s++) {
        const int k0 = s * 8;
        uint32_t a[4];
        a[0] = sxu[arow0 + k0];
        a[1] = sxu[arow1 + k0];
        a[2] = sxu[arow0 + k0 + 4];
        a[3] = sxu[arow1 + k0 + 4];
        #pragma unroll
        for (int j = 0; j < 4; j++) {
            uint32_t b[2];
            const int brow = (j * 8 + g) * XSTRIDE + k0 + c;
            b[0] = swtu[brow];
            b[1] = swtu[brow + 4];
            mma_tf32(acc[j], a, b);
        }
    }

    // ---- epilogue: thread owns rows {m0+g, m0+g+8}, cols {j*8+2c, j*8+2c+1} ----
    float sum0 = 0.0f, sum1 = 0.0f;
    #pragma unroll
    for (int j = 0; j < 4; j++) {
        const int col = j * 8 + c * 2;
        const float b1a = sb1[col],     w2a = sw2[col];
        const float b1b = sb1[col + 1], w2b = sw2[col + 1];
        sum0 = fmaf(elu_f(acc[j][0] + b1a), w2a, sum0);
        sum0 = fmaf(elu_f(acc[j][1] + b1b), w2b, sum0);
        sum1 = fmaf(elu_f(acc[j][2] + b1a), w2a, sum1);
        sum1 = fmaf(elu_f(acc[j][3] + b1b), w2b, sum1);
    }
    // reduce over the 4 lanes of the quad (lane%4)
    sum0 += __shfl_xor_sync(0xffffffffu, sum0, 1);
    sum0 += __shfl_xor_sync(0xffffffffu, sum0, 2);
    sum1 += __shfl_xor_sync(0xffffffffu, sum1, 1);
    sum1 += __shfl_xor_sync(0xffffffffu, sum1, 2);

    if (c == 0) {
        const float b2q = b2g[q];
        const int b0 = bt * BT + m0 + g;
        out[(size_t)b0 * Q_TOT + q]       = sum0 + b2q;
        out[(size_t)(b0 + 8) * Q_TOT + q] = sum1 + b2q;
    }
}

extern "C" void kernel_launch(void* const* d_in, const int* in_sizes, int n_in,
                              void* d_out, int out_size)
{
    const float* x  = (const float*)d_in[0];
    const float* w1 = (const float*)d_in[1];
    const float* b1 = (const float*)d_in[2];
    const float* w2 = (const float*)d_in[3];
    const float* b2 = (const float*)d_in[4];
    float* out = (float*)d_out;

    cudaFuncSetAttribute(divenc_mma_kernel,
                         cudaFuncAttributeMaxDynamicSharedMemorySize, SMEM_BYTES);

    dim3 grid(Q_TOT, B_TOT / BT);   // (128, 16)
    divenc_mma_kernel<<<grid, 256, SMEM_BYTES>>>(x, w1, b1, w2, b2, out);
}